// round 12
// baseline (speedup 1.0000x reference)
#include <cuda_runtime.h>
#include <cstdint>

// ---------------- problem constants ----------------
#define AA    2048
#define TT    91
#define DD    256
#define HH    4
#define DHH   64
#define KDD   1024
#define MROWS (AA*TT)               // 186368 = 1456 * 128 exactly
#define SEC   47710208L             // MROWS * DD

// ---------------- scratch (__device__ globals; no allocation) ----------------
__device__ float g_Y1[(size_t)MROWS * DD];   // attention output [A,T,D]
__device__ float g_S [(size_t)MROWS * DD];   // Y2 + x
__device__ float g_F1[(size_t)MROWS * KDD];  // FFN hidden
__device__ float g_F2[(size_t)MROWS * DD];   // pre-LN
__device__ int   g_mask_u8;                  // 1 if padding_mask stored as bytes

// ---------------- helpers ----------------
__device__ __forceinline__ unsigned f2tf(float f) {
    unsigned u;
    asm("cvt.rna.tf32.f32 %0, %1;" : "=r"(u) : "f"(f));
    return u;
}

__device__ __forceinline__ void mma8(float* c, const unsigned* a, const unsigned* b) {
    asm volatile(
        "mma.sync.aligned.m16n8k8.row.col.f32.tf32.tf32.f32 "
        "{%0,%1,%2,%3}, {%4,%5,%6,%7}, {%8,%9}, {%0,%1,%2,%3};"
        : "+f"(c[0]), "+f"(c[1]), "+f"(c[2]), "+f"(c[3])
        : "r"(a[0]), "r"(a[1]), "r"(a[2]), "r"(a[3]), "r"(b[0]), "r"(b[1]));
}

__device__ __forceinline__ unsigned sptr(const void* p) {
    return (unsigned)__cvta_generic_to_shared(p);
}

// ---------------- GEMM config: 256 threads, 8 warps, 64x32 warp tiles ----------------
#define BM 128
#define BN 128
#define BK 32
#define ASTR 36     // BK+4:  A-frag LDS banks (4g+tg)%32 -> conflict-free
#define BSTR 136    // BN+8:  B-frag LDS banks (8tg+g)%32 -> conflict-free
#define SMA (BM*ASTR)                 // 4608 floats
#define SMB (BK*BSTR)                 // 4352 floats
#define GEMM_SMEM ((2*(SMA+SMB))*4)   // 71680 bytes

// stage one (BMxBK A, BKxBN B) tile into smem buffer
__device__ __forceinline__ void stage_tile(
    const float* __restrict__ Ag, long lda, long rowBase, int kOff,
    const float* __restrict__ Bg, long ldb, int colBase,
    float* As, float* Bs, int tid)
{
#pragma unroll
    for (int j = 0; j < 4; j++) {
        const int idx = tid + j * 256;
        const int r = idx >> 3, c = (idx & 7) * 4;
        unsigned d = sptr(As) + (unsigned)((r * ASTR + c) * 4);
        asm volatile("cp.async.ca.shared.global [%0], [%1], 16;"
                     :: "r"(d), "l"(Ag + (rowBase + r) * lda + kOff + c));
    }
#pragma unroll
    for (int j = 0; j < 4; j++) {
        const int idx = tid + j * 256;
        const int r = idx >> 5, c = (idx & 31) * 4;
        unsigned d = sptr(Bs) + (unsigned)((r * BSTR + c) * 4);
        asm volatile("cp.async.ca.shared.global [%0], [%1], 16;"
                     :: "r"(d), "l"(Bg + (long)(kOff + r) * ldb + colBase + c));
    }
    asm volatile("cp.async.commit_group;");
}

// EPI: 0 = relu(c+bias) row-major
//      1 = relu(c+bias) -> transposed [A,H,T,DH] store
//      2 = EPI1 * scale_q[col&63]
//      3 = relu(c+bias) + extra[row,col] (residual)
template<int EPI>
__global__ void __launch_bounds__(256) gemm_kernel(
    const float* __restrict__ Ag, int lda,
    const float* __restrict__ Bg, int ldb,
    const float* __restrict__ bias,
    const float* __restrict__ extra,
    float* __restrict__ Cg, int ldc,
    int nk)
{
    extern __shared__ float sh[];
    float* As = sh;              // 2 * SMA
    float* Bs = sh + 2 * SMA;    // 2 * SMB

    const int tid  = threadIdx.x;
    const int lane = tid & 31, warp = tid >> 5;
    const int g = lane >> 2, tg = lane & 3;
    const int wm = (warp & 1) * 64;        // 2 row-groups of 64
    const int wn = (warp >> 1) * 32;       // 4 col-groups of 32
    const long rowBase = (long)blockIdx.x * BM;
    const int  colBase = blockIdx.y * BN;

    float acc[4][4][4];
#pragma unroll
    for (int i = 0; i < 4; i++)
#pragma unroll
        for (int j = 0; j < 4; j++)
#pragma unroll
            for (int l = 0; l < 4; l++) acc[i][j][l] = 0.f;

    stage_tile(Ag, lda, rowBase, 0, Bg, ldb, colBase, As, Bs, tid);

    for (int kt = 0; kt < nk; kt++) {
        const int cur = kt & 1;
        if (kt + 1 < nk) {
            const int nxt = cur ^ 1;
            stage_tile(Ag, lda, rowBase, (kt + 1) * BK, Bg, ldb, colBase,
                       As + nxt * SMA, Bs + nxt * SMB, tid);
            asm volatile("cp.async.wait_group 1;");
        } else {
            asm volatile("cp.async.wait_group 0;");
        }
        __syncthreads();

        const float* Ac = As + cur * SMA;
        const float* Bc = Bs + cur * SMB;
#pragma unroll
        for (int ks = 0; ks < 4; ks++) {
            const int k0 = ks * 8;
            unsigned afrag[4][4];
            unsigned bfrag[4][2];
#pragma unroll
            for (int mt = 0; mt < 4; mt++) {
                const int r = wm + mt * 16 + g;
                afrag[mt][0] = f2tf(Ac[r * ASTR + k0 + tg]);
                afrag[mt][1] = f2tf(Ac[(r + 8) * ASTR + k0 + tg]);
                afrag[mt][2] = f2tf(Ac[r * ASTR + k0 + tg + 4]);
                afrag[mt][3] = f2tf(Ac[(r + 8) * ASTR + k0 + tg + 4]);
            }
#pragma unroll
            for (int nt = 0; nt < 4; nt++) {
                const int n = wn + nt * 8 + g;
                bfrag[nt][0] = f2tf(Bc[(k0 + tg) * BSTR + n]);
                bfrag[nt][1] = f2tf(Bc[(k0 + tg + 4) * BSTR + n]);
            }
#pragma unroll
            for (int mt = 0; mt < 4; mt++)
#pragma unroll
                for (int nt = 0; nt < 4; nt++)
                    mma8(acc[mt][nt], afrag[mt], bfrag[nt]);
        }
        __syncthreads();
    }

    // epilogue
#pragma unroll
    for (int mt = 0; mt < 4; mt++) {
        const long r0 = rowBase + wm + mt * 16 + g;
        const long r1 = r0 + 8;
#pragma unroll
        for (int nt = 0; nt < 4; nt++) {
            const int c = colBase + wn + nt * 8 + 2 * tg;
            const float b0 = bias[c], b1 = bias[c + 1];
            float v00 = fmaxf(acc[mt][nt][0] + b0, 0.f);
            float v01 = fmaxf(acc[mt][nt][1] + b1, 0.f);
            float v10 = fmaxf(acc[mt][nt][2] + b0, 0.f);
            float v11 = fmaxf(acc[mt][nt][3] + b1, 0.f);
            if (EPI == 0) {
                *(float2*)(Cg + r0 * ldc + c) = make_float2(v00, v01);
                *(float2*)(Cg + r1 * ldc + c) = make_float2(v10, v11);
            } else if (EPI == 3) {
                float2 x0 = *(const float2*)(extra + r0 * ldc + c);
                float2 x1 = *(const float2*)(extra + r1 * ldc + c);
                *(float2*)(Cg + r0 * ldc + c) = make_float2(v00 + x0.x, v01 + x0.y);
                *(float2*)(Cg + r1 * ldc + c) = make_float2(v10 + x1.x, v11 + x1.y);
            } else {
                if (EPI == 2) {
                    const float s0 = extra[c & 63], s1 = extra[(c + 1) & 63];
                    v00 *= s0; v01 *= s1; v10 *= s0; v11 *= s1;
                }
                const int a0i = (int)(r0 / TT), t0 = (int)(r0 - (long)a0i * TT);
                const int a1i = (int)(r1 / TT), t1 = (int)(r1 - (long)a1i * TT);
                const int hh = c >> 6, dh = c & 63;
                const long o0 = (((long)a0i * HH + hh) * TT + t0) * DHH + dh;
                const long o1 = (((long)a1i * HH + hh) * TT + t1) * DHH + dh;
                *(float2*)(Cg + o0) = make_float2(v00, v01);
                *(float2*)(Cg + o1) = make_float2(v10, v11);
            }
        }
    }
}

// ---------------- mask layout detector ----------------
__global__ void detect_mask_kernel(const unsigned* __restrict__ m) {
    int u8 = 0;
    for (int i = 0; i < 64; i++)
        if (m[i] > 1u) u8 = 1;
    g_mask_u8 = u8;
}

// ---------------- attention: 256 threads, float4 inner products ----------------
#define QSTR 68      // floats; 68*4=272 bytes, 16B aligned, (4k+d)%32 banks -> conflict-free
#define ATT_SMEM ((3*TT*QSTR + 96 + 8*92) * 4)

__global__ void __launch_bounds__(256) attn_kernel(
    const float* __restrict__ Qp, const float* __restrict__ Kp,
    const float* __restrict__ Vp, const void* __restrict__ maskp,
    float* __restrict__ Y1)
{
    extern __shared__ float sh[];
    float* Qs = sh;
    float* Ks = Qs + TT * QSTR;
    float* Vs = Ks + TT * QSTR;
    float* ms = Vs + TT * QSTR;      // 96 slots
    float* probs = ms + 96;          // 8 warps * 92

    const int tid = threadIdx.x;
    const int ah = blockIdx.x;
    const int a = ah >> 2, h = ah & 3;

    const float* qb = Qp + (long)ah * (TT * DHH);
    const float* kb = Kp + (long)ah * (TT * DHH);
    const float* vb = Vp + (long)ah * (TT * DHH);

    for (int i = tid; i < TT * 16; i += 256) {       // 1456 float4 per tensor
        const int t = i >> 4, d = (i & 15) * 4;
        float4 q4 = *(const float4*)(qb + t * DHH + d);
        float4 k4 = *(const float4*)(kb + t * DHH + d);
        float4 v4 = *(const float4*)(vb + t * DHH + d);
        *(float4*)(Qs + t * QSTR + d) = q4;
        *(float4*)(Ks + t * QSTR + d) = k4;
        *(float4*)(Vs + t * QSTR + d) = v4;
    }
    if (tid < TT) {
        const long idx = (long)a * TT + tid;
        int v;
        if (g_mask_u8) v = ((const unsigned char*)maskp)[idx];
        else           v = ((const int*)maskp)[idx];
        ms[tid] = (v != 0) ? 1.f : 0.f;
    }
    __syncthreads();

    const int warp = tid >> 5, lane = tid & 31;
    float* pw = probs + warp * 92;
    const float invScale = 0.5f;     // 1/sqrt(H) = 1/2
    const float NEGV = -1e10f;

    for (int q = warp; q < TT; q += 8) {
        const float mq = ms[q];
        // Q row in registers (reused across all 91 keys)
        float4 qr[16];
#pragma unroll
        for (int i = 0; i < 16; i++)
            qr[i] = *(const float4*)(Qs + q * QSTR + i * 4);

        float e[3];
#pragma unroll
        for (int j = 0; j < 3; j++) {
            const int k = lane + 32 * j;
            if (k < TT) {
                const float4* kr = (const float4*)(Ks + k * QSTR);
                float dot = 0.f;
#pragma unroll
                for (int i = 0; i < 16; i++) {
                    const float4 kv = kr[i];
                    dot += qr[i].x * kv.x + qr[i].y * kv.y
                         + qr[i].z * kv.z + qr[i].w * kv.w;
                }
                e[j] = (mq > 0.f && ms[k] > 0.f) ? dot * invScale : NEGV;
            } else {
                e[j] = -3.0e38f;
            }
        }
        float mx = fmaxf(e[0], fmaxf(e[1], e[2]));
#pragma unroll
        for (int o = 16; o; o >>= 1)
            mx = fmaxf(mx, __shfl_xor_sync(0xFFFFFFFFu, mx, o));
        float p[3], s = 0.f;
#pragma unroll
        for (int j = 0; j < 3; j++) {
            const int k = lane + 32 * j;
            p[j] = (k < TT) ? expf(e[j] - mx) : 0.f;
            s += p[j];
        }
#pragma unroll
        for (int o = 16; o; o >>= 1)
            s += __shfl_xor_sync(0xFFFFFFFFu, s, o);
        const float inv = 1.f / s;
#pragma unroll
        for (int j = 0; j < 3; j++) {
            const int k = lane + 32 * j;
            if (k < TT) pw[k] = p[j] * inv;
        }
        __syncwarp();

        float y0 = 0.f, y1 = 0.f;
#pragma unroll 7
        for (int k = 0; k < TT; k++) {
            const float pk = pw[k];
            y0 += pk * Vs[k * QSTR + lane];
            y1 += pk * Vs[k * QSTR + lane + 32];
        }
        float* yd = Y1 + ((long)(a * TT + q)) * DD + h * DHH;
        yd[lane]      = y0;
        yd[lane + 32] = y1;
        __syncwarp();
    }
}

// ---------------- layernorm ----------------
__global__ void __launch_bounds__(256) ln_kernel(
    const float* __restrict__ F2, const float* __restrict__ gg,
    const float* __restrict__ bb, float* __restrict__ Z)
{
    const int warp = threadIdx.x >> 5, lane = threadIdx.x & 31;
    const long row = (long)blockIdx.x * 8 + warp;
    const float4* src = (const float4*)(F2 + row * DD);
    float4 v0 = src[lane], v1 = src[lane + 32];
    float s  = v0.x + v0.y + v0.z + v0.w + v1.x + v1.y + v1.z + v1.w;
    float sq = v0.x*v0.x + v0.y*v0.y + v0.z*v0.z + v0.w*v0.w
             + v1.x*v1.x + v1.y*v1.y + v1.z*v1.z + v1.w*v1.w;
#pragma unroll
    for (int o = 16; o; o >>= 1) {
        s  += __shfl_xor_sync(0xFFFFFFFFu, s,  o);
        sq += __shfl_xor_sync(0xFFFFFFFFu, sq, o);
    }
    const float mu  = s * (1.f / DD);
    const float var = sq * (1.f / DD) - mu * mu;
    const float rs  = rsqrtf(var + 1e-5f);
    const float4* g4 = (const float4*)gg;
    const float4* b4 = (const float4*)bb;
    float4* dst = (float4*)(Z + row * DD);
#pragma unroll
    for (int half = 0; half < 2; half++) {
        const float4 v = half ? v1 : v0;
        const float4 g = g4[lane + half * 32];
        const float4 b = b4[lane + half * 32];
        float4 z;
        z.x = (v.x - mu) * rs * g.x + b.x;
        z.y = (v.y - mu) * rs * g.y + b.y;
        z.z = (v.z - mu) * rs * g.z + b.z;
        z.w = (v.w - mu) * rs * g.w + b.w;
        dst[lane + half * 32] = z;
    }
}

// ---------------- launch ----------------
extern "C" void kernel_launch(void* const* d_in, const int* in_sizes, int n_in,
                              void* d_out, int out_size) {
    const float* x       = (const float*)d_in[0];
    const void*  pm      = d_in[2];
    const float* W_K     = (const float*)d_in[3];
    const float* b_K     = (const float*)d_in[4];
    const float* W_V     = (const float*)d_in[5];
    const float* b_V     = (const float*)d_in[6];
    const float* W_Q0    = (const float*)d_in[7];
    const float* b_Q0    = (const float*)d_in[8];
    const float* scale_q = (const float*)d_in[9];
    const float* W_Y2    = (const float*)d_in[10];
    const float* b_Y2    = (const float*)d_in[11];
    const float* W_F1    = (const float*)d_in[12];
    const float* b_F1    = (const float*)d_in[13];
    const float* W_F2    = (const float*)d_in[14];
    const float* b_F2    = (const float*)d_in[15];
    const float* ln_g    = (const float*)d_in[16];
    const float* ln_b    = (const float*)d_in[17];

    float* out = (float*)d_out;
    float* Z  = out;
    float* Qp = out + SEC;
    float* Kp = out + 2 * SEC;
    float* Vp = out + 3 * SEC;

    void *pY1, *pS, *pF1, *pF2;
    cudaGetSymbolAddress(&pY1, g_Y1);
    cudaGetSymbolAddress(&pS,  g_S);
    cudaGetSymbolAddress(&pF1, g_F1);
    cudaGetSymbolAddress(&pF2, g_F2);
    float* Y1g = (float*)pY1;
    float* Sg  = (float*)pS;
    float* F1g = (float*)pF1;
    float* F2g = (float*)pF2;

    cudaFuncSetAttribute(gemm_kernel<0>, cudaFuncAttributeMaxDynamicSharedMemorySize, GEMM_SMEM);
    cudaFuncSetAttribute(gemm_kernel<1>, cudaFuncAttributeMaxDynamicSharedMemorySize, GEMM_SMEM);
    cudaFuncSetAttribute(gemm_kernel<2>, cudaFuncAttributeMaxDynamicSharedMemorySize, GEMM_SMEM);
    cudaFuncSetAttribute(gemm_kernel<3>, cudaFuncAttributeMaxDynamicSharedMemorySize, GEMM_SMEM);
    cudaFuncSetAttribute(attn_kernel,    cudaFuncAttributeMaxDynamicSharedMemorySize, ATT_SMEM);

    const dim3 gproj(MROWS / BM, DD / BN);    // (1456, 2)
    const dim3 gf1  (MROWS / BM, KDD / BN);   // (1456, 8)

    detect_mask_kernel<<<1, 1>>>((const unsigned*)pm);

    // QKV projections -> transposed stores straight into d_out sections
    gemm_kernel<1><<<gproj, 256, GEMM_SMEM>>>(x, DD, W_K,  DD, b_K,  nullptr, Kp, 0, DD / BK);
    gemm_kernel<1><<<gproj, 256, GEMM_SMEM>>>(x, DD, W_V,  DD, b_V,  nullptr, Vp, 0, DD / BK);
    gemm_kernel<2><<<gproj, 256, GEMM_SMEM>>>(x, DD, W_Q0, DD, b_Q0, scale_q, Qp, 0, DD / BK);

    attn_kernel<<<AA * HH, 256, ATT_SMEM>>>(Qp, Kp, Vp, pm, Y1g);

    // Y2 + residual
    gemm_kernel<3><<<gproj, 256, GEMM_SMEM>>>(Y1g, DD, W_Y2, DD, b_Y2, x, Sg, DD, DD / BK);
    // F1
    gemm_kernel<0><<<gf1, 256, GEMM_SMEM>>>(Sg, DD, W_F1, KDD, b_F1, nullptr, F1g, KDD, DD / BK);
    // F2
    gemm_kernel<0><<<gproj, 256, GEMM_SMEM>>>(F1g, KDD, W_F2, DD, b_F2, nullptr, F2g, DD, KDD / BK);
    // LayerNorm -> Z
    ln_kernel<<<MROWS / 8, 256>>>(F2g, ln_g, ln_b, Z);
}

// round 13
// speedup vs baseline: 1.1008x; 1.1008x over previous
#include <cuda_runtime.h>
#include <cstdint>

// ---------------- problem constants ----------------
#define AA    2048
#define TT    91
#define DD    256
#define HH    4
#define DHH   64
#define KDD   1024
#define MROWS (AA*TT)               // 186368 = 1456 * 128 exactly
#define SEC   47710208L             // MROWS * DD

// ---------------- scratch (__device__ globals; no allocation) ----------------
__device__ float g_Y1[(size_t)MROWS * DD];   // attention output [A,T,D]
__device__ float g_S [(size_t)MROWS * DD];   // Y2 + x
__device__ float g_F1[(size_t)MROWS * KDD];  // FFN hidden
__device__ float g_F2[(size_t)MROWS * DD];   // pre-LN
__device__ int   g_mask_u8;                  // 1 if padding_mask stored as bytes

// ---------------- helpers ----------------
__device__ __forceinline__ unsigned f2tf(float f) {
    unsigned u;
    asm("cvt.rna.tf32.f32 %0, %1;" : "=r"(u) : "f"(f));
    return u;
}

__device__ __forceinline__ void mma8(float* c, const unsigned* a, const unsigned* b) {
    asm volatile(
        "mma.sync.aligned.m16n8k8.row.col.f32.tf32.tf32.f32 "
        "{%0,%1,%2,%3}, {%4,%5,%6,%7}, {%8,%9}, {%0,%1,%2,%3};"
        : "+f"(c[0]), "+f"(c[1]), "+f"(c[2]), "+f"(c[3])
        : "r"(a[0]), "r"(a[1]), "r"(a[2]), "r"(a[3]), "r"(b[0]), "r"(b[1]));
}

__device__ __forceinline__ unsigned sptr(const void* p) {
    return (unsigned)__cvta_generic_to_shared(p);
}

// ---------------- GEMM config: 256 threads, 8 warps, 64x32 warp tiles ----------------
#define BM 128
#define BN 128
#define BK 32
#define ASTR 36     // BK+4:  A-frag LDS banks (4g+tg)%32 -> conflict-free
#define BSTR 136    // BN+8:  B-frag LDS banks (8tg+g)%32 -> conflict-free
#define SMA (BM*ASTR)                 // 4608 floats
#define SMB (BK*BSTR)                 // 4352 floats
#define GEMM_SMEM ((2*(SMA+SMB))*4)   // 71680 bytes; x2 CTAs = 143KB < 228KB

// stage one (BMxBK A, BKxBN B) tile into smem buffer (.cg: bypass L1)
__device__ __forceinline__ void stage_tile(
    const float* __restrict__ Ag, long lda, long rowBase, int kOff,
    const float* __restrict__ Bg, long ldb, int colBase,
    float* As, float* Bs, int tid)
{
#pragma unroll
    for (int j = 0; j < 4; j++) {
        const int idx = tid + j * 256;
        const int r = idx >> 3, c = (idx & 7) * 4;
        unsigned d = sptr(As) + (unsigned)((r * ASTR + c) * 4);
        asm volatile("cp.async.cg.shared.global [%0], [%1], 16;"
                     :: "r"(d), "l"(Ag + (rowBase + r) * lda + kOff + c));
    }
#pragma unroll
    for (int j = 0; j < 4; j++) {
        const int idx = tid + j * 256;
        const int r = idx >> 5, c = (idx & 31) * 4;
        unsigned d = sptr(Bs) + (unsigned)((r * BSTR + c) * 4);
        asm volatile("cp.async.cg.shared.global [%0], [%1], 16;"
                     :: "r"(d), "l"(Bg + (long)(kOff + r) * ldb + colBase + c));
    }
    asm volatile("cp.async.commit_group;");
}

// EPI: 0 = relu(c+bias) row-major
//      1 = relu(c+bias) -> transposed [A,H,T,DH] store
//      2 = EPI1 * scale_q[col&63]
//      3 = relu(c+bias) + extra[row,col] (residual)
template<int EPI>
__global__ void __launch_bounds__(256, 2) gemm_kernel(
    const float* __restrict__ Ag, int lda,
    const float* __restrict__ Bg, int ldb,
    const float* __restrict__ bias,
    const float* __restrict__ extra,
    float* __restrict__ Cg, int ldc,
    int nk)
{
    extern __shared__ float sh[];
    float* As = sh;              // 2 * SMA
    float* Bs = sh + 2 * SMA;    // 2 * SMB

    const int tid  = threadIdx.x;
    const int lane = tid & 31, warp = tid >> 5;
    const int g = lane >> 2, tg = lane & 3;
    const int wm = (warp & 1) * 64;        // 2 row-groups of 64
    const int wn = (warp >> 1) * 32;       // 4 col-groups of 32
    const long rowBase = (long)blockIdx.x * BM;
    const int  colBase = blockIdx.y * BN;

    float acc[4][4][4];
#pragma unroll
    for (int i = 0; i < 4; i++)
#pragma unroll
        for (int j = 0; j < 4; j++)
#pragma unroll
            for (int l = 0; l < 4; l++) acc[i][j][l] = 0.f;

    stage_tile(Ag, lda, rowBase, 0, Bg, ldb, colBase, As, Bs, tid);

    for (int kt = 0; kt < nk; kt++) {
        const int cur = kt & 1;
        if (kt + 1 < nk) {
            const int nxt = cur ^ 1;
            stage_tile(Ag, lda, rowBase, (kt + 1) * BK, Bg, ldb, colBase,
                       As + nxt * SMA, Bs + nxt * SMB, tid);
            asm volatile("cp.async.wait_group 1;");
        } else {
            asm volatile("cp.async.wait_group 0;");
        }
        __syncthreads();

        const float* Ac = As + cur * SMA;
        const float* Bc = Bs + cur * SMB;
#pragma unroll
        for (int ks = 0; ks < 4; ks++) {
            const int k0 = ks * 8;
            unsigned afrag[4][4];
            unsigned bfrag[4][2];
#pragma unroll
            for (int mt = 0; mt < 4; mt++) {
                const int r = wm + mt * 16 + g;
                afrag[mt][0] = f2tf(Ac[r * ASTR + k0 + tg]);
                afrag[mt][1] = f2tf(Ac[(r + 8) * ASTR + k0 + tg]);
                afrag[mt][2] = f2tf(Ac[r * ASTR + k0 + tg + 4]);
                afrag[mt][3] = f2tf(Ac[(r + 8) * ASTR + k0 + tg + 4]);
            }
#pragma unroll
            for (int nt = 0; nt < 4; nt++) {
                const int n = wn + nt * 8 + g;
                bfrag[nt][0] = f2tf(Bc[(k0 + tg) * BSTR + n]);
                bfrag[nt][1] = f2tf(Bc[(k0 + tg + 4) * BSTR + n]);
            }
#pragma unroll
            for (int mt = 0; mt < 4; mt++)
#pragma unroll
                for (int nt = 0; nt < 4; nt++)
                    mma8(acc[mt][nt], afrag[mt], bfrag[nt]);
        }
        __syncthreads();
    }

    // epilogue
#pragma unroll
    for (int mt = 0; mt < 4; mt++) {
        const long r0 = rowBase + wm + mt * 16 + g;
        const long r1 = r0 + 8;
#pragma unroll
        for (int nt = 0; nt < 4; nt++) {
            const int c = colBase + wn + nt * 8 + 2 * tg;
            const float b0 = bias[c], b1 = bias[c + 1];
            float v00 = fmaxf(acc[mt][nt][0] + b0, 0.f);
            float v01 = fmaxf(acc[mt][nt][1] + b1, 0.f);
            float v10 = fmaxf(acc[mt][nt][2] + b0, 0.f);
            float v11 = fmaxf(acc[mt][nt][3] + b1, 0.f);
            if (EPI == 0) {
                *(float2*)(Cg + r0 * ldc + c) = make_float2(v00, v01);
                *(float2*)(Cg + r1 * ldc + c) = make_float2(v10, v11);
            } else if (EPI == 3) {
                float2 x0 = *(const float2*)(extra + r0 * ldc + c);
                float2 x1 = *(const float2*)(extra + r1 * ldc + c);
                *(float2*)(Cg + r0 * ldc + c) = make_float2(v00 + x0.x, v01 + x0.y);
                *(float2*)(Cg + r1 * ldc + c) = make_float2(v10 + x1.x, v11 + x1.y);
            } else {
                if (EPI == 2) {
                    const float s0 = extra[c & 63], s1 = extra[(c + 1) & 63];
                    v00 *= s0; v01 *= s1; v10 *= s0; v11 *= s1;
                }
                const int a0i = (int)(r0 / TT), t0 = (int)(r0 - (long)a0i * TT);
                const int a1i = (int)(r1 / TT), t1 = (int)(r1 - (long)a1i * TT);
                const int hh = c >> 6, dh = c & 63;
                const long o0 = (((long)a0i * HH + hh) * TT + t0) * DHH + dh;
                const long o1 = (((long)a1i * HH + hh) * TT + t1) * DHH + dh;
                *(float2*)(Cg + o0) = make_float2(v00, v01);
                *(float2*)(Cg + o1) = make_float2(v10, v11);
            }
        }
    }
}

// ---------------- mask layout detector ----------------
__global__ void detect_mask_kernel(const unsigned* __restrict__ m) {
    int u8 = 0;
    for (int i = 0; i < 64; i++)
        if (m[i] > 1u) u8 = 1;
    g_mask_u8 = u8;
}

// ---------------- attention: 256 threads, float4 inner products ----------------
#define QSTR 68      // floats; 16B aligned, (4k+d)%32 banks -> conflict-free
#define ATT_SMEM ((3*TT*QSTR + 96 + 8*92) * 4)

__global__ void __launch_bounds__(256) attn_kernel(
    const float* __restrict__ Qp, const float* __restrict__ Kp,
    const float* __restrict__ Vp, const void* __restrict__ maskp,
    float* __restrict__ Y1)
{
    extern __shared__ float sh[];
    float* Qs = sh;
    float* Ks = Qs + TT * QSTR;
    float* Vs = Ks + TT * QSTR;
    float* ms = Vs + TT * QSTR;      // 96 slots
    float* probs = ms + 96;          // 8 warps * 92

    const int tid = threadIdx.x;
    const int ah = blockIdx.x;
    const int a = ah >> 2, h = ah & 3;

    const float* qb = Qp + (long)ah * (TT * DHH);
    const float* kb = Kp + (long)ah * (TT * DHH);
    const float* vb = Vp + (long)ah * (TT * DHH);

    for (int i = tid; i < TT * 16; i += 256) {       // 1456 float4 per tensor
        const int t = i >> 4, d = (i & 15) * 4;
        float4 q4 = *(const float4*)(qb + t * DHH + d);
        float4 k4 = *(const float4*)(kb + t * DHH + d);
        float4 v4 = *(const float4*)(vb + t * DHH + d);
        *(float4*)(Qs + t * QSTR + d) = q4;
        *(float4*)(Ks + t * QSTR + d) = k4;
        *(float4*)(Vs + t * QSTR + d) = v4;
    }
    if (tid < TT) {
        const long idx = (long)a * TT + tid;
        int v;
        if (g_mask_u8) v = ((const unsigned char*)maskp)[idx];
        else           v = ((const int*)maskp)[idx];
        ms[tid] = (v != 0) ? 1.f : 0.f;
    }
    __syncthreads();

    const int warp = tid >> 5, lane = tid & 31;
    float* pw = probs + warp * 92;
    const float invScale = 0.5f;     // 1/sqrt(H) = 1/2
    const float NEGV = -1e10f;

    for (int q = warp; q < TT; q += 8) {
        const float mq = ms[q];
        float4 qr[16];
#pragma unroll
        for (int i = 0; i < 16; i++)
            qr[i] = *(const float4*)(Qs + q * QSTR + i * 4);

        float e[3];
#pragma unroll
        for (int j = 0; j < 3; j++) {
            const int k = lane + 32 * j;
            if (k < TT) {
                const float4* kr = (const float4*)(Ks + k * QSTR);
                float dot = 0.f;
#pragma unroll
                for (int i = 0; i < 16; i++) {
                    const float4 kv = kr[i];
                    dot += qr[i].x * kv.x + qr[i].y * kv.y
                         + qr[i].z * kv.z + qr[i].w * kv.w;
                }
                e[j] = (mq > 0.f && ms[k] > 0.f) ? dot * invScale : NEGV;
            } else {
                e[j] = -3.0e38f;
            }
        }
        float mx = fmaxf(e[0], fmaxf(e[1], e[2]));
#pragma unroll
        for (int o = 16; o; o >>= 1)
            mx = fmaxf(mx, __shfl_xor_sync(0xFFFFFFFFu, mx, o));
        float p[3], s = 0.f;
#pragma unroll
        for (int j = 0; j < 3; j++) {
            const int k = lane + 32 * j;
            p[j] = (k < TT) ? __expf(e[j] - mx) : 0.f;
            s += p[j];
        }
#pragma unroll
        for (int o = 16; o; o >>= 1)
            s += __shfl_xor_sync(0xFFFFFFFFu, s, o);
        const float inv = 1.f / s;
#pragma unroll
        for (int j = 0; j < 3; j++) {
            const int k = lane + 32 * j;
            if (k < TT) pw[k] = p[j] * inv;
        }
        __syncwarp();

        float y0 = 0.f, y1 = 0.f;
#pragma unroll 7
        for (int k = 0; k < TT; k++) {
            const float pk = pw[k];
            y0 += pk * Vs[k * QSTR + lane];
            y1 += pk * Vs[k * QSTR + lane + 32];
        }
        float* yd = Y1 + ((long)(a * TT + q)) * DD + h * DHH;
        yd[lane]      = y0;
        yd[lane + 32] = y1;
        __syncwarp();
    }
}

// ---------------- layernorm ----------------
__global__ void __launch_bounds__(256) ln_kernel(
    const float* __restrict__ F2, const float* __restrict__ gg,
    const float* __restrict__ bb, float* __restrict__ Z)
{
    const int warp = threadIdx.x >> 5, lane = threadIdx.x & 31;
    const long row = (long)blockIdx.x * 8 + warp;
    const float4* src = (const float4*)(F2 + row * DD);
    float4 v0 = src[lane], v1 = src[lane + 32];
    float s  = v0.x + v0.y + v0.z + v0.w + v1.x + v1.y + v1.z + v1.w;
    float sq = v0.x*v0.x + v0.y*v0.y + v0.z*v0.z + v0.w*v0.w
             + v1.x*v1.x + v1.y*v1.y + v1.z*v1.z + v1.w*v1.w;
#pragma unroll
    for (int o = 16; o; o >>= 1) {
        s  += __shfl_xor_sync(0xFFFFFFFFu, s,  o);
        sq += __shfl_xor_sync(0xFFFFFFFFu, sq, o);
    }
    const float mu  = s * (1.f / DD);
    const float var = sq * (1.f / DD) - mu * mu;
    const float rs  = rsqrtf(var + 1e-5f);
    const float4* g4 = (const float4*)gg;
    const float4* b4 = (const float4*)bb;
    float4* dst = (float4*)(Z + row * DD);
#pragma unroll
    for (int half = 0; half < 2; half++) {
        const float4 v = half ? v1 : v0;
        const float4 g = g4[lane + half * 32];
        const float4 b = b4[lane + half * 32];
        float4 z;
        z.x = (v.x - mu) * rs * g.x + b.x;
        z.y = (v.y - mu) * rs * g.y + b.y;
        z.z = (v.z - mu) * rs * g.z + b.z;
        z.w = (v.w - mu) * rs * g.w + b.w;
        dst[lane + half * 32] = z;
    }
}

// ---------------- launch ----------------
extern "C" void kernel_launch(void* const* d_in, const int* in_sizes, int n_in,
                              void* d_out, int out_size) {
    const float* x       = (const float*)d_in[0];
    const void*  pm      = d_in[2];
    const float* W_K     = (const float*)d_in[3];
    const float* b_K     = (const float*)d_in[4];
    const float* W_V     = (const float*)d_in[5];
    const float* b_V     = (const float*)d_in[6];
    const float* W_Q0    = (const float*)d_in[7];
    const float* b_Q0    = (const float*)d_in[8];
    const float* scale_q = (const float*)d_in[9];
    const float* W_Y2    = (const float*)d_in[10];
    const float* b_Y2    = (const float*)d_in[11];
    const float* W_F1    = (const float*)d_in[12];
    const float* b_F1    = (const float*)d_in[13];
    const float* W_F2    = (const float*)d_in[14];
    const float* b_F2    = (const float*)d_in[15];
    const float* ln_g    = (const float*)d_in[16];
    const float* ln_b    = (const float*)d_in[17];

    float* out = (float*)d_out;
    float* Z  = out;
    float* Qp = out + SEC;
    float* Kp = out + 2 * SEC;
    float* Vp = out + 3 * SEC;

    void *pY1, *pS, *pF1, *pF2;
    cudaGetSymbolAddress(&pY1, g_Y1);
    cudaGetSymbolAddress(&pS,  g_S);
    cudaGetSymbolAddress(&pF1, g_F1);
    cudaGetSymbolAddress(&pF2, g_F2);
    float* Y1g = (float*)pY1;
    float* Sg  = (float*)pS;
    float* F1g = (float*)pF1;
    float* F2g = (float*)pF2;

    cudaFuncSetAttribute(gemm_kernel<0>, cudaFuncAttributeMaxDynamicSharedMemorySize, GEMM_SMEM);
    cudaFuncSetAttribute(gemm_kernel<1>, cudaFuncAttributeMaxDynamicSharedMemorySize, GEMM_SMEM);
    cudaFuncSetAttribute(gemm_kernel<2>, cudaFuncAttributeMaxDynamicSharedMemorySize, GEMM_SMEM);
    cudaFuncSetAttribute(gemm_kernel<3>, cudaFuncAttributeMaxDynamicSharedMemorySize, GEMM_SMEM);
    cudaFuncSetAttribute(attn_kernel,    cudaFuncAttributeMaxDynamicSharedMemorySize, ATT_SMEM);

    const dim3 gproj(MROWS / BM, DD / BN);    // (1456, 2)
    const dim3 gf1  (MROWS / BM, KDD / BN);   // (1456, 8)

    detect_mask_kernel<<<1, 1>>>((const unsigned*)pm);

    // QKV projections -> transposed stores straight into d_out sections
    gemm_kernel<1><<<gproj, 256, GEMM_SMEM>>>(x, DD, W_K,  DD, b_K,  nullptr, Kp, 0, DD / BK);
    gemm_kernel<1><<<gproj, 256, GEMM_SMEM>>>(x, DD, W_V,  DD, b_V,  nullptr, Vp, 0, DD / BK);
    gemm_kernel<2><<<gproj, 256, GEMM_SMEM>>>(x, DD, W_Q0, DD, b_Q0, scale_q, Qp, 0, DD / BK);

    attn_kernel<<<AA * HH, 256, ATT_SMEM>>>(Qp, Kp, Vp, pm, Y1g);

    // Y2 + residual
    gemm_kernel<3><<<gproj, 256, GEMM_SMEM>>>(Y1g, DD, W_Y2, DD, b_Y2, x, Sg, DD, DD / BK);
    // F1
    gemm_kernel<0><<<gf1, 256, GEMM_SMEM>>>(Sg, DD, W_F1, KDD, b_F1, nullptr, F1g, KDD, DD / BK);
    // F2
    gemm_kernel<0><<<gproj, 256, GEMM_SMEM>>>(F1g, KDD, W_F2, DD, b_F2, nullptr, F2g, DD, KDD / BK);
    // LayerNorm -> Z
    ln_kernel<<<MROWS / 8, 256>>>(F2g, ln_g, ln_b, Z);
}

// round 14
// speedup vs baseline: 1.1242x; 1.0212x over previous
#include <cuda_runtime.h>
#include <cstdint>

// ---------------- problem constants ----------------
#define AA    2048
#define TT    91
#define DD    256
#define HH    4
#define DHH   64
#define KDD   1024
#define MROWS (AA*TT)               // 186368 = 1456 * 128 exactly
#define SEC   47710208L             // MROWS * DD

// ---------------- scratch (__device__ globals; no allocation) ----------------
__device__ float g_Y1[(size_t)MROWS * DD];   // attention output [A,T,D] (tf32-rounded)
__device__ float g_S [(size_t)MROWS * DD];   // Y2 + x (tf32-rounded)
__device__ float g_F1[(size_t)MROWS * KDD];  // FFN hidden (tf32-rounded)
__device__ float g_F2[(size_t)MROWS * DD];   // pre-LN (full fp32)
__device__ float g_xr[(size_t)MROWS * DD];   // tf32-rounded copy of x
__device__ float g_W [786432];               // tf32-rounded weights, packed
__device__ int   g_mask_u8;                  // 1 if padding_mask stored as bytes

// packed weight offsets (floats)
#define OW_K   0
#define OW_V   65536
#define OW_Q   131072
#define OW_Y2  196608
#define OW_F1  262144
#define OW_F2  524288

// ---------------- helpers ----------------
__device__ __forceinline__ unsigned f2tf(float f) {
    unsigned u;
    asm("cvt.rna.tf32.f32 %0, %1;" : "=r"(u) : "f"(f));
    return u;
}
__device__ __forceinline__ float rnd_tf(float f) { return __uint_as_float(f2tf(f)); }

__device__ __forceinline__ void mma8(float* c, const unsigned* a, const unsigned* b) {
    asm volatile(
        "mma.sync.aligned.m16n8k8.row.col.f32.tf32.tf32.f32 "
        "{%0,%1,%2,%3}, {%4,%5,%6,%7}, {%8,%9}, {%0,%1,%2,%3};"
        : "+f"(c[0]), "+f"(c[1]), "+f"(c[2]), "+f"(c[3])
        : "r"(a[0]), "r"(a[1]), "r"(a[2]), "r"(a[3]), "r"(b[0]), "r"(b[1]));
}

__device__ __forceinline__ unsigned sptr(const void* p) {
    return (unsigned)__cvta_generic_to_shared(p);
}

// ---------------- tf32 pre-round kernel (float4) ----------------
__global__ void __launch_bounds__(256) round_kernel(
    const float4* __restrict__ src, float4* __restrict__ dst, int n4)
{
    const int i = blockIdx.x * 256 + threadIdx.x;
    if (i < n4) {
        float4 v = src[i];
        v.x = rnd_tf(v.x); v.y = rnd_tf(v.y);
        v.z = rnd_tf(v.z); v.w = rnd_tf(v.w);
        dst[i] = v;
    }
}

// ---------------- GEMM config: 256 threads, 8 warps, 64x32 warp tiles ----------------
#define BM 128
#define BN 128
#define BK 32
#define ASTR 36     // BK+4:  A-frag LDS banks (4g+tg)%32 -> conflict-free
#define BSTR 136    // BN+8:  B-frag LDS banks (8tg+g)%32 -> conflict-free
#define SMA (BM*ASTR)                 // 4608 floats
#define SMB (BK*BSTR)                 // 4352 floats
#define GEMM_SMEM ((2*(SMA+SMB))*4)   // 71680 bytes; x2 CTAs = 143KB < 228KB

// stage one (BMxBK A, BKxBN B) tile into smem buffer (.cg: bypass L1)
__device__ __forceinline__ void stage_tile(
    const float* __restrict__ Ag, long lda, long rowBase, int kOff,
    const float* __restrict__ Bg, long ldb, int colBase,
    float* As, float* Bs, int tid)
{
#pragma unroll
    for (int j = 0; j < 4; j++) {
        const int idx = tid + j * 256;
        const int r = idx >> 3, c = (idx & 7) * 4;
        unsigned d = sptr(As) + (unsigned)((r * ASTR + c) * 4);
        asm volatile("cp.async.cg.shared.global [%0], [%1], 16;"
                     :: "r"(d), "l"(Ag + (rowBase + r) * lda + kOff + c));
    }
#pragma unroll
    for (int j = 0; j < 4; j++) {
        const int idx = tid + j * 256;
        const int r = idx >> 5, c = (idx & 31) * 4;
        unsigned d = sptr(Bs) + (unsigned)((r * BSTR + c) * 4);
        asm volatile("cp.async.cg.shared.global [%0], [%1], 16;"
                     :: "r"(d), "l"(Bg + (long)(kOff + r) * ldb + colBase + c));
    }
    asm volatile("cp.async.commit_group;");
}

// EPI: 0 = relu(c+bias) row-major, tf32-rounded store (feeds a GEMM-A)
//      1 = relu(c+bias) -> transposed [A,H,T,DH] store (full fp32, output)
//      2 = EPI1 * scale_q[col&63] (full fp32, output)
//      3 = relu(c+bias) + extra[row,col], tf32-rounded store (feeds a GEMM-A)
//      4 = relu(c+bias) row-major, FULL fp32 (pre-LN F2)
template<int EPI>
__global__ void __launch_bounds__(256, 2) gemm_kernel(
    const float* __restrict__ Ag, int lda,
    const float* __restrict__ Bg, int ldb,
    const float* __restrict__ bias,
    const float* __restrict__ extra,
    float* __restrict__ Cg, int ldc,
    int nk)
{
    extern __shared__ float sh[];
    float* As = sh;              // 2 * SMA
    float* Bs = sh + 2 * SMA;    // 2 * SMB

    const int tid  = threadIdx.x;
    const int lane = tid & 31, warp = tid >> 5;
    const int g = lane >> 2, tg = lane & 3;
    const int wm = (warp & 1) * 64;        // 2 row-groups of 64
    const int wn = (warp >> 1) * 32;       // 4 col-groups of 32
    const long rowBase = (long)blockIdx.x * BM;
    const int  colBase = blockIdx.y * BN;

    float acc[4][4][4];
#pragma unroll
    for (int i = 0; i < 4; i++)
#pragma unroll
        for (int j = 0; j < 4; j++)
#pragma unroll
            for (int l = 0; l < 4; l++) acc[i][j][l] = 0.f;

    stage_tile(Ag, lda, rowBase, 0, Bg, ldb, colBase, As, Bs, tid);

    for (int kt = 0; kt < nk; kt++) {
        const int cur = kt & 1;
        if (kt + 1 < nk) {
            const int nxt = cur ^ 1;
            stage_tile(Ag, lda, rowBase, (kt + 1) * BK, Bg, ldb, colBase,
                       As + nxt * SMA, Bs + nxt * SMB, tid);
            asm volatile("cp.async.wait_group 1;");
        } else {
            asm volatile("cp.async.wait_group 0;");
        }
        __syncthreads();

        // data in smem is ALREADY tf32-rounded -> raw bit reinterpret, no cvt
        const unsigned* Ac = (const unsigned*)(As + cur * SMA);
        const unsigned* Bc = (const unsigned*)(Bs + cur * SMB);
#pragma unroll
        for (int ks = 0; ks < 4; ks++) {
            const int k0 = ks * 8;
            unsigned afrag[4][4];
            unsigned bfrag[4][2];
#pragma unroll
            for (int mt = 0; mt < 4; mt++) {
                const int r = wm + mt * 16 + g;
                afrag[mt][0] = Ac[r * ASTR + k0 + tg];
                afrag[mt][1] = Ac[(r + 8) * ASTR + k0 + tg];
                afrag[mt][2] = Ac[r * ASTR + k0 + tg + 4];
                afrag[mt][3] = Ac[(r + 8) * ASTR + k0 + tg + 4];
            }
#pragma unroll
            for (int nt = 0; nt < 4; nt++) {
                const int n = wn + nt * 8 + g;
                bfrag[nt][0] = Bc[(k0 + tg) * BSTR + n];
                bfrag[nt][1] = Bc[(k0 + tg + 4) * BSTR + n];
            }
#pragma unroll
            for (int mt = 0; mt < 4; mt++)
#pragma unroll
                for (int nt = 0; nt < 4; nt++)
                    mma8(acc[mt][nt], afrag[mt], bfrag[nt]);
        }
        __syncthreads();
    }

    // epilogue
#pragma unroll
    for (int mt = 0; mt < 4; mt++) {
        const long r0 = rowBase + wm + mt * 16 + g;
        const long r1 = r0 + 8;
#pragma unroll
        for (int nt = 0; nt < 4; nt++) {
            const int c = colBase + wn + nt * 8 + 2 * tg;
            const float b0 = bias[c], b1 = bias[c + 1];
            float v00 = fmaxf(acc[mt][nt][0] + b0, 0.f);
            float v01 = fmaxf(acc[mt][nt][1] + b1, 0.f);
            float v10 = fmaxf(acc[mt][nt][2] + b0, 0.f);
            float v11 = fmaxf(acc[mt][nt][3] + b1, 0.f);
            if (EPI == 0) {
                *(float2*)(Cg + r0 * ldc + c) = make_float2(rnd_tf(v00), rnd_tf(v01));
                *(float2*)(Cg + r1 * ldc + c) = make_float2(rnd_tf(v10), rnd_tf(v11));
            } else if (EPI == 4) {
                *(float2*)(Cg + r0 * ldc + c) = make_float2(v00, v01);
                *(float2*)(Cg + r1 * ldc + c) = make_float2(v10, v11);
            } else if (EPI == 3) {
                float2 x0 = *(const float2*)(extra + r0 * ldc + c);
                float2 x1 = *(const float2*)(extra + r1 * ldc + c);
                *(float2*)(Cg + r0 * ldc + c) = make_float2(rnd_tf(v00 + x0.x), rnd_tf(v01 + x0.y));
                *(float2*)(Cg + r1 * ldc + c) = make_float2(rnd_tf(v10 + x1.x), rnd_tf(v11 + x1.y));
            } else {
                if (EPI == 2) {
                    const float s0 = extra[c & 63], s1 = extra[(c + 1) & 63];
                    v00 *= s0; v01 *= s1; v10 *= s0; v11 *= s1;
                }
                const int a0i = (int)(r0 / TT), t0 = (int)(r0 - (long)a0i * TT);
                const int a1i = (int)(r1 / TT), t1 = (int)(r1 - (long)a1i * TT);
                const int hh = c >> 6, dh = c & 63;
                const long o0 = (((long)a0i * HH + hh) * TT + t0) * DHH + dh;
                const long o1 = (((long)a1i * HH + hh) * TT + t1) * DHH + dh;
                *(float2*)(Cg + o0) = make_float2(v00, v01);
                *(float2*)(Cg + o1) = make_float2(v10, v11);
            }
        }
    }
}

// ---------------- mask layout detector ----------------
__global__ void detect_mask_kernel(const unsigned* __restrict__ m) {
    int u8 = 0;
    for (int i = 0; i < 64; i++)
        if (m[i] > 1u) u8 = 1;
    g_mask_u8 = u8;
}

// ---------------- attention: 256 threads, float4 inner products ----------------
#define QSTR 68      // floats; 16B aligned, (4k+d)%32 banks -> conflict-free
#define ATT_SMEM ((3*TT*QSTR + 96 + 8*92) * 4)

__global__ void __launch_bounds__(256) attn_kernel(
    const float* __restrict__ Qp, const float* __restrict__ Kp,
    const float* __restrict__ Vp, const void* __restrict__ maskp,
    float* __restrict__ Y1)
{
    extern __shared__ float sh[];
    float* Qs = sh;
    float* Ks = Qs + TT * QSTR;
    float* Vs = Ks + TT * QSTR;
    float* ms = Vs + TT * QSTR;      // 96 slots
    float* probs = ms + 96;          // 8 warps * 92

    const int tid = threadIdx.x;
    const int ah = blockIdx.x;
    const int a = ah >> 2, h = ah & 3;

    const float* qb = Qp + (long)ah * (TT * DHH);
    const float* kb = Kp + (long)ah * (TT * DHH);
    const float* vb = Vp + (long)ah * (TT * DHH);

    for (int i = tid; i < TT * 16; i += 256) {       // 1456 float4 per tensor
        const int t = i >> 4, d = (i & 15) * 4;
        float4 q4 = *(const float4*)(qb + t * DHH + d);
        float4 k4 = *(const float4*)(kb + t * DHH + d);
        float4 v4 = *(const float4*)(vb + t * DHH + d);
        *(float4*)(Qs + t * QSTR + d) = q4;
        *(float4*)(Ks + t * QSTR + d) = k4;
        *(float4*)(Vs + t * QSTR + d) = v4;
    }
    if (tid < TT) {
        const long idx = (long)a * TT + tid;
        int v;
        if (g_mask_u8) v = ((const unsigned char*)maskp)[idx];
        else           v = ((const int*)maskp)[idx];
        ms[tid] = (v != 0) ? 1.f : 0.f;
    }
    __syncthreads();

    const int warp = tid >> 5, lane = tid & 31;
    float* pw = probs + warp * 92;
    const float invScale = 0.5f;     // 1/sqrt(H) = 1/2
    const float NEGV = -1e10f;

    for (int q = warp; q < TT; q += 8) {
        const float mq = ms[q];
        float4 qr[16];
#pragma unroll
        for (int i = 0; i < 16; i++)
            qr[i] = *(const float4*)(Qs + q * QSTR + i * 4);

        float e[3];
#pragma unroll
        for (int j = 0; j < 3; j++) {
            const int k = lane + 32 * j;
            if (k < TT) {
                const float4* kr = (const float4*)(Ks + k * QSTR);
                float dot = 0.f;
#pragma unroll
                for (int i = 0; i < 16; i++) {
                    const float4 kv = kr[i];
                    dot += qr[i].x * kv.x + qr[i].y * kv.y
                         + qr[i].z * kv.z + qr[i].w * kv.w;
                }
                e[j] = (mq > 0.f && ms[k] > 0.f) ? dot * invScale : NEGV;
            } else {
                e[j] = -3.0e38f;
            }
        }
        float mx = fmaxf(e[0], fmaxf(e[1], e[2]));
#pragma unroll
        for (int o = 16; o; o >>= 1)
            mx = fmaxf(mx, __shfl_xor_sync(0xFFFFFFFFu, mx, o));
        float p[3], s = 0.f;
#pragma unroll
        for (int j = 0; j < 3; j++) {
            const int k = lane + 32 * j;
            p[j] = (k < TT) ? __expf(e[j] - mx) : 0.f;
            s += p[j];
        }
#pragma unroll
        for (int o = 16; o; o >>= 1)
            s += __shfl_xor_sync(0xFFFFFFFFu, s, o);
        const float inv = 1.f / s;
#pragma unroll
        for (int j = 0; j < 3; j++) {
            const int k = lane + 32 * j;
            if (k < TT) pw[k] = p[j] * inv;
        }
        __syncwarp();

        float y0 = 0.f, y1 = 0.f;
#pragma unroll 7
        for (int k = 0; k < TT; k++) {
            const float pk = pw[k];
            y0 += pk * Vs[k * QSTR + lane];
            y1 += pk * Vs[k * QSTR + lane + 32];
        }
        // Y1 feeds only the Y2 GEMM-A: store tf32-rounded
        float* yd = Y1 + ((long)(a * TT + q)) * DD + h * DHH;
        yd[lane]      = rnd_tf(y0);
        yd[lane + 32] = rnd_tf(y1);
        __syncwarp();
    }
}

// ---------------- layernorm ----------------
__global__ void __launch_bounds__(256) ln_kernel(
    const float* __restrict__ F2, const float* __restrict__ gg,
    const float* __restrict__ bb, float* __restrict__ Z)
{
    const int warp = threadIdx.x >> 5, lane = threadIdx.x & 31;
    const long row = (long)blockIdx.x * 8 + warp;
    const float4* src = (const float4*)(F2 + row * DD);
    float4 v0 = src[lane], v1 = src[lane + 32];
    float s  = v0.x + v0.y + v0.z + v0.w + v1.x + v1.y + v1.z + v1.w;
    float sq = v0.x*v0.x + v0.y*v0.y + v0.z*v0.z + v0.w*v0.w
             + v1.x*v1.x + v1.y*v1.y + v1.z*v1.z + v1.w*v1.w;
#pragma unroll
    for (int o = 16; o; o >>= 1) {
        s  += __shfl_xor_sync(0xFFFFFFFFu, s,  o);
        sq += __shfl_xor_sync(0xFFFFFFFFu, sq, o);
    }
    const float mu  = s * (1.f / DD);
    const float var = sq * (1.f / DD) - mu * mu;
    const float rs  = rsqrtf(var + 1e-5f);
    const float4* g4 = (const float4*)gg;
    const float4* b4 = (const float4*)bb;
    float4* dst = (float4*)(Z + row * DD);
#pragma unroll
    for (int half = 0; half < 2; half++) {
        const float4 v = half ? v1 : v0;
        const float4 g = g4[lane + half * 32];
        const float4 b = b4[lane + half * 32];
        float4 z;
        z.x = (v.x - mu) * rs * g.x + b.x;
        z.y = (v.y - mu) * rs * g.y + b.y;
        z.z = (v.z - mu) * rs * g.z + b.z;
        z.w = (v.w - mu) * rs * g.w + b.w;
        dst[lane + half * 32] = z;
    }
}

// ---------------- launch ----------------
extern "C" void kernel_launch(void* const* d_in, const int* in_sizes, int n_in,
                              void* d_out, int out_size) {
    const float* x       = (const float*)d_in[0];
    const void*  pm      = d_in[2];
    const float* W_K     = (const float*)d_in[3];
    const float* b_K     = (const float*)d_in[4];
    const float* W_V     = (const float*)d_in[5];
    const float* b_V     = (const float*)d_in[6];
    const float* W_Q0    = (const float*)d_in[7];
    const float* b_Q0    = (const float*)d_in[8];
    const float* scale_q = (const float*)d_in[9];
    const float* W_Y2    = (const float*)d_in[10];
    const float* b_Y2    = (const float*)d_in[11];
    const float* W_F1    = (const float*)d_in[12];
    const float* b_F1    = (const float*)d_in[13];
    const float* W_F2    = (const float*)d_in[14];
    const float* b_F2    = (const float*)d_in[15];
    const float* ln_g    = (const float*)d_in[16];
    const float* ln_b    = (const float*)d_in[17];

    float* out = (float*)d_out;
    float* Z  = out;
    float* Qp = out + SEC;
    float* Kp = out + 2 * SEC;
    float* Vp = out + 3 * SEC;

    void *pY1, *pS, *pF1, *pF2, *pXr, *pW;
    cudaGetSymbolAddress(&pY1, g_Y1);
    cudaGetSymbolAddress(&pS,  g_S);
    cudaGetSymbolAddress(&pF1, g_F1);
    cudaGetSymbolAddress(&pF2, g_F2);
    cudaGetSymbolAddress(&pXr, g_xr);
    cudaGetSymbolAddress(&pW,  g_W);
    float* Y1g = (float*)pY1;
    float* Sg  = (float*)pS;
    float* F1g = (float*)pF1;
    float* F2g = (float*)pF2;
    float* Xr  = (float*)pXr;
    float* Wr  = (float*)pW;

    cudaFuncSetAttribute(gemm_kernel<0>, cudaFuncAttributeMaxDynamicSharedMemorySize, GEMM_SMEM);
    cudaFuncSetAttribute(gemm_kernel<1>, cudaFuncAttributeMaxDynamicSharedMemorySize, GEMM_SMEM);
    cudaFuncSetAttribute(gemm_kernel<2>, cudaFuncAttributeMaxDynamicSharedMemorySize, GEMM_SMEM);
    cudaFuncSetAttribute(gemm_kernel<3>, cudaFuncAttributeMaxDynamicSharedMemorySize, GEMM_SMEM);
    cudaFuncSetAttribute(gemm_kernel<4>, cudaFuncAttributeMaxDynamicSharedMemorySize, GEMM_SMEM);
    cudaFuncSetAttribute(attn_kernel,    cudaFuncAttributeMaxDynamicSharedMemorySize, ATT_SMEM);

    const dim3 gproj(MROWS / BM, DD / BN);    // (1456, 2)
    const dim3 gf1  (MROWS / BM, KDD / BN);   // (1456, 8)

    detect_mask_kernel<<<1, 1>>>((const unsigned*)pm);

    // pre-round weights + x to tf32 (consumer GEMMs then skip cvt entirely)
    round_kernel<<<64,  256>>>((const float4*)W_K,  (float4*)(Wr + OW_K),  16384);
    round_kernel<<<64,  256>>>((const float4*)W_V,  (float4*)(Wr + OW_V),  16384);
    round_kernel<<<64,  256>>>((const float4*)W_Q0, (float4*)(Wr + OW_Q),  16384);
    round_kernel<<<64,  256>>>((const float4*)W_Y2, (float4*)(Wr + OW_Y2), 16384);
    round_kernel<<<256, 256>>>((const float4*)W_F1, (float4*)(Wr + OW_F1), 65536);
    round_kernel<<<256, 256>>>((const float4*)W_F2, (float4*)(Wr + OW_F2), 65536);
    round_kernel<<<46592, 256>>>((const float4*)x,  (float4*)Xr, (int)(SEC / 4));

    // QKV projections -> transposed stores straight into d_out sections
    gemm_kernel<1><<<gproj, 256, GEMM_SMEM>>>(Xr, DD, Wr + OW_K, DD, b_K,  nullptr, Kp, 0, DD / BK);
    gemm_kernel<1><<<gproj, 256, GEMM_SMEM>>>(Xr, DD, Wr + OW_V, DD, b_V,  nullptr, Vp, 0, DD / BK);
    gemm_kernel<2><<<gproj, 256, GEMM_SMEM>>>(Xr, DD, Wr + OW_Q, DD, b_Q0, scale_q, Qp, 0, DD / BK);

    attn_kernel<<<AA * HH, 256, ATT_SMEM>>>(Qp, Kp, Vp, pm, Y1g);

    // Y2 + residual (x full precision for the residual add)
    gemm_kernel<3><<<gproj, 256, GEMM_SMEM>>>(Y1g, DD, Wr + OW_Y2, DD, b_Y2, x, Sg, DD, DD / BK);
    // F1
    gemm_kernel<0><<<gf1, 256, GEMM_SMEM>>>(Sg, DD, Wr + OW_F1, KDD, b_F1, nullptr, F1g, KDD, DD / BK);
    // F2 (full fp32 out, feeds LN)
    gemm_kernel<4><<<gproj, 256, GEMM_SMEM>>>(F1g, KDD, Wr + OW_F2, DD, b_F2, nullptr, F2g, DD, KDD / BK);
    // LayerNorm -> Z
    ln_kernel<<<MROWS / 8, 256>>>(F2g, ln_g, ln_b, Z);
}

// round 16
// speedup vs baseline: 1.4278x; 1.2700x over previous
#include <cuda_runtime.h>
#include <cuda_fp16.h>
#include <cstdint>

// ---------------- problem constants ----------------
#define AA    2048
#define TT    91
#define DD    256
#define HH    4
#define DHH   64
#define KDD   1024
#define MROWS (AA*TT)               // 186368 = 1456 * 128 exactly
#define SEC   47710208L             // MROWS * DD

// ---------------- scratch (__device__ globals; no allocation) ----------------
__device__ __half g_Y1h[(size_t)MROWS * DD];   // attention output [A,T,D] (fp16)
__device__ __half g_Sh [(size_t)MROWS * DD];   // Y2 + x (fp16)
__device__ __half g_F1h[(size_t)MROWS * KDD];  // FFN hidden (fp16)
__device__ float  g_F2 [(size_t)MROWS * DD];   // pre-LN (fp32)
__device__ __half g_xh [(size_t)MROWS * DD];   // fp16 copy of x
__device__ __half g_Wh [786432];               // fp16 weights, packed
__device__ int    g_mask_u8;                   // 1 if padding_mask stored as bytes

// packed weight offsets (halves)
#define OW_K   0
#define OW_V   65536
#define OW_Q   131072
#define OW_Y2  196608
#define OW_F1  262144
#define OW_F2  524288

// ---------------- helpers ----------------
__device__ __forceinline__ unsigned sptr(const void* p) {
    return (unsigned)__cvta_generic_to_shared(p);
}

__device__ __forceinline__ void mma16(float* c, const unsigned* a, const unsigned* b) {
    asm volatile(
        "mma.sync.aligned.m16n8k16.row.col.f32.f16.f16.f32 "
        "{%0,%1,%2,%3}, {%4,%5,%6,%7}, {%8,%9}, {%0,%1,%2,%3};"
        : "+f"(c[0]), "+f"(c[1]), "+f"(c[2]), "+f"(c[3])
        : "r"(a[0]), "r"(a[1]), "r"(a[2]), "r"(a[3]), "r"(b[0]), "r"(b[1]));
}

// ---------------- fp32 -> fp16 conversion pre-pass ----------------
__global__ void __launch_bounds__(256) cvt_kernel(
    const float4* __restrict__ src, __half2* __restrict__ dst, int n4)
{
    const int i = blockIdx.x * 256 + threadIdx.x;
    if (i < n4) {
        float4 v = src[i];
        dst[2 * i]     = __floats2half2_rn(v.x, v.y);
        dst[2 * i + 1] = __floats2half2_rn(v.z, v.w);
    }
}

// ---------------- GEMM config: 256 threads, 8 warps, 64x32 warp tiles ----------------
#define BM 128
#define BN 128
#define BK 32
#define ASTRH 40     // halves; row word-offsets 20r%32 = {0,20,8,28,16,4,24,12} -> LDSM conflict-free
#define BSTRH 136    // halves; row word-offsets 68k%32 = 4k -> LDSM conflict-free
#define SMAH (BM*ASTRH)                 // 5120 halves
#define SMBH (BK*BSTRH)                 // 4352 halves
#define GEMM_SMEM ((2*(SMAH+SMBH))*2)   // 37888 bytes; x2 CTAs = 76KB

// stage one (BMxBK A, BKxBN B) fp16 tile into smem
__device__ __forceinline__ void stage_tile(
    const __half* __restrict__ Ag, long lda, long rowBase, int kOff,
    const __half* __restrict__ Bg, long ldb, int colBase,
    __half* As, __half* Bs, int tid)
{
#pragma unroll
    for (int j = 0; j < 2; j++) {
        const int idx = tid + j * 256;
        const int r = idx >> 2, c = (idx & 3) * 8;
        unsigned d = sptr(As) + (unsigned)((r * ASTRH + c) * 2);
        asm volatile("cp.async.cg.shared.global [%0], [%1], 16;"
                     :: "r"(d), "l"(Ag + (rowBase + r) * lda + kOff + c));
    }
#pragma unroll
    for (int j = 0; j < 2; j++) {
        const int idx = tid + j * 256;
        const int r = idx >> 4, c = (idx & 15) * 8;
        unsigned d = sptr(Bs) + (unsigned)((r * BSTRH + c) * 2);
        asm volatile("cp.async.cg.shared.global [%0], [%1], 16;"
                     :: "r"(d), "l"(Bg + (long)(kOff + r) * ldb + colBase + c));
    }
    asm volatile("cp.async.commit_group;");
}

// EPI: 0 = relu(c+bias) row-major, fp16 store (feeds next GEMM-A)
//      1 = relu(c+bias) -> transposed [A,H,T,DH] fp32 store (K/V outputs)
//      2 = EPI1 * scale_q[col&63] (Q output, fp32)
//      3 = relu(c+bias) + extra[row,col], fp16 store (S)
//      4 = relu(c+bias) row-major fp32 (F2, feeds LN)
template<int EPI>
__global__ void __launch_bounds__(256, 2) gemm_kernel(
    const __half* __restrict__ Ag, int lda,
    const __half* __restrict__ Bg, int ldb,
    const float* __restrict__ bias,
    const float* __restrict__ extra,
    float* __restrict__ Cg, int ldc,
    int nk)
{
    extern __shared__ char smem_raw[];
    __half* As = (__half*)smem_raw;   // 2 * SMAH
    __half* Bs = As + 2 * SMAH;       // 2 * SMBH

    const int tid  = threadIdx.x;
    const int lane = tid & 31, warp = tid >> 5;
    const int g = lane >> 2, tg = lane & 3;
    const int wm = (warp & 1) * 64;        // 2 row-groups of 64
    const int wn = (warp >> 1) * 32;       // 4 col-groups of 32
    const long rowBase = (long)blockIdx.x * BM;
    const int  colBase = blockIdx.y * BN;

    // ldmatrix lane addressing
    const int lrow = lane & 15;            // row within 16-row tile
    const int kblk = (lane >> 4) * 8;      // k half-block for A x4

    float acc[4][4][4];
#pragma unroll
    for (int i = 0; i < 4; i++)
#pragma unroll
        for (int j = 0; j < 4; j++)
#pragma unroll
            for (int l = 0; l < 4; l++) acc[i][j][l] = 0.f;

    stage_tile(Ag, lda, rowBase, 0, Bg, ldb, colBase, As, Bs, tid);

    for (int kt = 0; kt < nk; kt++) {
        const int cur = kt & 1;
        if (kt + 1 < nk) {
            const int nxt = cur ^ 1;
            stage_tile(Ag, lda, rowBase, (kt + 1) * BK, Bg, ldb, colBase,
                       As + nxt * SMAH, Bs + nxt * SMBH, tid);
            asm volatile("cp.async.wait_group 1;");
        } else {
            asm volatile("cp.async.wait_group 0;");
        }
        __syncthreads();

        const __half* Ac = As + cur * SMAH;
        const __half* Bc = Bs + cur * SMBH;
#pragma unroll
        for (int ks = 0; ks < 2; ks++) {
            const int k0 = ks * 16;
            unsigned afrag[4][4];
            unsigned bfrag[4][2];
#pragma unroll
            for (int mt = 0; mt < 4; mt++) {
                unsigned addr = sptr(Ac + (wm + mt * 16 + lrow) * ASTRH + k0 + kblk);
                asm volatile(
                    "ldmatrix.sync.aligned.m8n8.x4.shared.b16 {%0,%1,%2,%3}, [%4];"
                    : "=r"(afrag[mt][0]), "=r"(afrag[mt][1]),
                      "=r"(afrag[mt][2]), "=r"(afrag[mt][3])
                    : "r"(addr));
            }
#pragma unroll
            for (int nt = 0; nt < 4; nt++) {
                unsigned addr = sptr(Bc + (k0 + lrow) * BSTRH + wn + nt * 8);
                asm volatile(
                    "ldmatrix.sync.aligned.m8n8.x2.trans.shared.b16 {%0,%1}, [%2];"
                    : "=r"(bfrag[nt][0]), "=r"(bfrag[nt][1])
                    : "r"(addr));
            }
#pragma unroll
            for (int mt = 0; mt < 4; mt++)
#pragma unroll
                for (int nt = 0; nt < 4; nt++)
                    mma16(acc[mt][nt], afrag[mt], bfrag[nt]);
        }
        __syncthreads();
    }

    // epilogue (acc layout: c0,c1=(row g, cols 2tg..+1); c2,c3=(row g+8, same cols))
#pragma unroll
    for (int mt = 0; mt < 4; mt++) {
        const long r0 = rowBase + wm + mt * 16 + g;
        const long r1 = r0 + 8;
#pragma unroll
        for (int nt = 0; nt < 4; nt++) {
            const int c = colBase + wn + nt * 8 + 2 * tg;
            const float b0 = bias[c], b1 = bias[c + 1];
            float v00 = fmaxf(acc[mt][nt][0] + b0, 0.f);
            float v01 = fmaxf(acc[mt][nt][1] + b1, 0.f);
            float v10 = fmaxf(acc[mt][nt][2] + b0, 0.f);
            float v11 = fmaxf(acc[mt][nt][3] + b1, 0.f);
            if (EPI == 0) {
                __half* Ch = (__half*)Cg;
                *(__half2*)(Ch + r0 * ldc + c) = __floats2half2_rn(v00, v01);
                *(__half2*)(Ch + r1 * ldc + c) = __floats2half2_rn(v10, v11);
            } else if (EPI == 3) {
                __half* Ch = (__half*)Cg;
                float2 x0 = *(const float2*)(extra + r0 * ldc + c);
                float2 x1 = *(const float2*)(extra + r1 * ldc + c);
                *(__half2*)(Ch + r0 * ldc + c) = __floats2half2_rn(v00 + x0.x, v01 + x0.y);
                *(__half2*)(Ch + r1 * ldc + c) = __floats2half2_rn(v10 + x1.x, v11 + x1.y);
            } else if (EPI == 4) {
                *(float2*)(Cg + r0 * ldc + c) = make_float2(v00, v01);
                *(float2*)(Cg + r1 * ldc + c) = make_float2(v10, v11);
            } else {
                if (EPI == 2) {
                    const float s0 = extra[c & 63], s1 = extra[(c + 1) & 63];
                    v00 *= s0; v01 *= s1; v10 *= s0; v11 *= s1;
                }
                const int a0i = (int)(r0 / TT), t0 = (int)(r0 - (long)a0i * TT);
                const int a1i = (int)(r1 / TT), t1 = (int)(r1 - (long)a1i * TT);
                const int hh = c >> 6, dh = c & 63;
                const long o0 = (((long)a0i * HH + hh) * TT + t0) * DHH + dh;
                const long o1 = (((long)a1i * HH + hh) * TT + t1) * DHH + dh;
                *(float2*)(Cg + o0) = make_float2(v00, v01);
                *(float2*)(Cg + o1) = make_float2(v10, v11);
            }
        }
    }
}

// ---------------- mask layout detector ----------------
__global__ void detect_mask_kernel(const unsigned* __restrict__ m) {
    int u8 = 0;
    for (int i = 0; i < 64; i++)
        if (m[i] > 1u) u8 = 1;
    g_mask_u8 = u8;
}

// ---------------- attention: 256 threads, float4 inner products ----------------
#define QSTR 68      // floats; 16B aligned, conflict-free
#define ATT_SMEM ((3*TT*QSTR + 96 + 8*92) * 4)

__global__ void __launch_bounds__(256) attn_kernel(
    const float* __restrict__ Qp, const float* __restrict__ Kp,
    const float* __restrict__ Vp, const void* __restrict__ maskp,
    __half* __restrict__ Y1)
{
    extern __shared__ char smem_raw[];
    float* Qs = (float*)smem_raw;
    float* Ks = Qs + TT * QSTR;
    float* Vs = Ks + TT * QSTR;
    float* ms = Vs + TT * QSTR;      // 96 slots
    float* probs = ms + 96;          // 8 warps * 92

    const int tid = threadIdx.x;
    const int ah = blockIdx.x;
    const int a = ah >> 2, h = ah & 3;

    const float* qb = Qp + (long)ah * (TT * DHH);
    const float* kb = Kp + (long)ah * (TT * DHH);
    const float* vb = Vp + (long)ah * (TT * DHH);

    for (int i = tid; i < TT * 16; i += 256) {       // 1456 float4 per tensor
        const int t = i >> 4, d = (i & 15) * 4;
        float4 q4 = *(const float4*)(qb + t * DHH + d);
        float4 k4 = *(const float4*)(kb + t * DHH + d);
        float4 v4 = *(const float4*)(vb + t * DHH + d);
        *(float4*)(Qs + t * QSTR + d) = q4;
        *(float4*)(Ks + t * QSTR + d) = k4;
        *(float4*)(Vs + t * QSTR + d) = v4;
    }
    if (tid < TT) {
        const long idx = (long)a * TT + tid;
        int v;
        if (g_mask_u8) v = ((const unsigned char*)maskp)[idx];
        else           v = ((const int*)maskp)[idx];
        ms[tid] = (v != 0) ? 1.f : 0.f;
    }
    __syncthreads();

    const int warp = tid >> 5, lane = tid & 31;
    float* pw = probs + warp * 92;
    const float invScale = 0.5f;     // 1/sqrt(H) = 1/2
    const float NEGV = -1e10f;

    for (int q = warp; q < TT; q += 8) {
        const float mq = ms[q];
        float4 qr[16];
#pragma unroll
        for (int i = 0; i < 16; i++)
            qr[i] = *(const float4*)(Qs + q * QSTR + i * 4);

        float e[3];
#pragma unroll
        for (int j = 0; j < 3; j++) {
            const int k = lane + 32 * j;
            if (k < TT) {
                const float4* kr = (const float4*)(Ks + k * QSTR);
                float dot = 0.f;
#pragma unroll
                for (int i = 0; i < 16; i++) {
                    const float4 kv = kr[i];
                    dot += qr[i].x * kv.x + qr[i].y * kv.y
                         + qr[i].z * kv.z + qr[i].w * kv.w;
                }
                e[j] = (mq > 0.f && ms[k] > 0.f) ? dot * invScale : NEGV;
            } else {
                e[j] = -3.0e38f;
            }
        }
        float mx = fmaxf(e[0], fmaxf(e[1], e[2]));
#pragma unroll
        for (int o = 16; o; o >>= 1)
            mx = fmaxf(mx, __shfl_xor_sync(0xFFFFFFFFu, mx, o));
        float p[3], s = 0.f;
#pragma unroll
        for (int j = 0; j < 3; j++) {
            const int k = lane + 32 * j;
            p[j] = (k < TT) ? __expf(e[j] - mx) : 0.f;
            s += p[j];
        }
#pragma unroll
        for (int o = 16; o; o >>= 1)
            s += __shfl_xor_sync(0xFFFFFFFFu, s, o);
        const float inv = 1.f / s;
#pragma unroll
        for (int j = 0; j < 3; j++) {
            const int k = lane + 32 * j;
            if (k < TT) pw[k] = p[j] * inv;
        }
        __syncwarp();

        float y0 = 0.f, y1 = 0.f;
#pragma unroll 7
        for (int k = 0; k < TT; k++) {
            const float pk = pw[k];
            y0 += pk * Vs[k * QSTR + lane];
            y1 += pk * Vs[k * QSTR + lane + 32];
        }
        // Y1 feeds only the Y2 GEMM-A -> fp16 store
        __half* yd = Y1 + ((long)(a * TT + q)) * DD + h * DHH;
        yd[lane]      = __float2half_rn(y0);
        yd[lane + 32] = __float2half_rn(y1);
        __syncwarp();
    }
}

// ---------------- layernorm ----------------
__global__ void __launch_bounds__(256) ln_kernel(
    const float* __restrict__ F2, const float* __restrict__ gg,
    const float* __restrict__ bb, float* __restrict__ Z)
{
    const int warp = threadIdx.x >> 5, lane = threadIdx.x & 31;
    const long row = (long)blockIdx.x * 8 + warp;
    const float4* src = (const float4*)(F2 + row * DD);
    float4 v0 = src[lane], v1 = src[lane + 32];
    float s  = v0.x + v0.y + v0.z + v0.w + v1.x + v1.y + v1.z + v1.w;
    float sq = v0.x*v0.x + v0.y*v0.y + v0.z*v0.z + v0.w*v0.w
             + v1.x*v1.x + v1.y*v1.y + v1.z*v1.z + v1.w*v1.w;
#pragma unroll
    for (int o = 16; o; o >>= 1) {
        s  += __shfl_xor_sync(0xFFFFFFFFu, s,  o);
        sq += __shfl_xor_sync(0xFFFFFFFFu, sq, o);
    }
    const float mu  = s * (1.f / DD);
    const float var = sq * (1.f / DD) - mu * mu;
    const float rs  = rsqrtf(var + 1e-5f);
    const float4* g4 = (const float4*)gg;
    const float4* b4 = (const float4*)bb;
    float4* dst = (float4*)(Z + row * DD);
#pragma unroll
    for (int half = 0; half < 2; half++) {
        const float4 v = half ? v1 : v0;
        const float4 g = g4[lane + half * 32];
        const float4 b = b4[lane + half * 32];
        float4 z;
        z.x = (v.x - mu) * rs * g.x + b.x;
        z.y = (v.y - mu) * rs * g.y + b.y;
        z.z = (v.z - mu) * rs * g.z + b.z;
        z.w = (v.w - mu) * rs * g.w + b.w;
        dst[lane + half * 32] = z;
    }
}

// ---------------- launch ----------------
extern "C" void kernel_launch(void* const* d_in, const int* in_sizes, int n_in,
                              void* d_out, int out_size) {
    const float* x       = (const float*)d_in[0];
    const void*  pm      = d_in[2];
    const float* W_K     = (const float*)d_in[3];
    const float* b_K     = (const float*)d_in[4];
    const float* W_V     = (const float*)d_in[5];
    const float* b_V     = (const float*)d_in[6];
    const float* W_Q0    = (const float*)d_in[7];
    const float* b_Q0    = (const float*)d_in[8];
    const float* scale_q = (const float*)d_in[9];
    const float* W_Y2    = (const float*)d_in[10];
    const float* b_Y2    = (const float*)d_in[11];
    const float* W_F1    = (const float*)d_in[12];
    const float* b_F1    = (const float*)d_in[13];
    const float* W_F2    = (const float*)d_in[14];
    const float* b_F2    = (const float*)d_in[15];
    const float* ln_g    = (const float*)d_in[16];
    const float* ln_b    = (const float*)d_in[17];

    float* out = (float*)d_out;
    float* Z  = out;
    float* Qp = out + SEC;
    float* Kp = out + 2 * SEC;
    float* Vp = out + 3 * SEC;

    void *pY1, *pS, *pF1, *pF2, *pXh, *pW;
    cudaGetSymbolAddress(&pY1, g_Y1h);
    cudaGetSymbolAddress(&pS,  g_Sh);
    cudaGetSymbolAddress(&pF1, g_F1h);
    cudaGetSymbolAddress(&pF2, g_F2);
    cudaGetSymbolAddress(&pXh, g_xh);
    cudaGetSymbolAddress(&pW,  g_Wh);
    __half* Y1h = (__half*)pY1;
    __half* Sh  = (__half*)pS;
    __half* F1h = (__half*)pF1;
    float*  F2g = (float*)pF2;
    __half* Xh  = (__half*)pXh;
    __half* Wh  = (__half*)pW;

    cudaFuncSetAttribute(gemm_kernel<0>, cudaFuncAttributeMaxDynamicSharedMemorySize, GEMM_SMEM);
    cudaFuncSetAttribute(gemm_kernel<1>, cudaFuncAttributeMaxDynamicSharedMemorySize, GEMM_SMEM);
    cudaFuncSetAttribute(gemm_kernel<2>, cudaFuncAttributeMaxDynamicSharedMemorySize, GEMM_SMEM);
    cudaFuncSetAttribute(gemm_kernel<3>, cudaFuncAttributeMaxDynamicSharedMemorySize, GEMM_SMEM);
    cudaFuncSetAttribute(gemm_kernel<4>, cudaFuncAttributeMaxDynamicSharedMemorySize, GEMM_SMEM);
    cudaFuncSetAttribute(attn_kernel,    cudaFuncAttributeMaxDynamicSharedMemorySize, ATT_SMEM);

    const dim3 gproj(MROWS / BM, DD / BN);    // (1456, 2)
    const dim3 gf1  (MROWS / BM, KDD / BN);   // (1456, 8)

    detect_mask_kernel<<<1, 1>>>((const unsigned*)pm);

    // fp32 -> fp16 conversion of weights + x
    cvt_kernel<<<64,  256>>>((const float4*)W_K,  (__half2*)(Wh + OW_K),  16384);
    cvt_kernel<<<64,  256>>>((const float4*)W_V,  (__half2*)(Wh + OW_V),  16384);
    cvt_kernel<<<64,  256>>>((const float4*)W_Q0, (__half2*)(Wh + OW_Q),  16384);
    cvt_kernel<<<64,  256>>>((const float4*)W_Y2, (__half2*)(Wh + OW_Y2), 16384);
    cvt_kernel<<<256, 256>>>((const float4*)W_F1, (__half2*)(Wh + OW_F1), 65536);
    cvt_kernel<<<256, 256>>>((const float4*)W_F2, (__half2*)(Wh + OW_F2), 65536);
    cvt_kernel<<<46592, 256>>>((const float4*)x,  (__half2*)Xh, (int)(SEC / 4));

    // QKV projections -> transposed fp32 stores straight into d_out sections
    gemm_kernel<1><<<gproj, 256, GEMM_SMEM>>>(Xh, DD, Wh + OW_K, DD, b_K,  nullptr, Kp, 0, DD / BK);
    gemm_kernel<1><<<gproj, 256, GEMM_SMEM>>>(Xh, DD, Wh + OW_V, DD, b_V,  nullptr, Vp, 0, DD / BK);
    gemm_kernel<2><<<gproj, 256, GEMM_SMEM>>>(Xh, DD, Wh + OW_Q, DD, b_Q0, scale_q, Qp, 0, DD / BK);

    attn_kernel<<<AA * HH, 256, ATT_SMEM>>>(Qp, Kp, Vp, pm, Y1h);

    // Y2 + residual (x fp32 for the residual add), S stored fp16
    gemm_kernel<3><<<gproj, 256, GEMM_SMEM>>>(Y1h, DD, Wh + OW_Y2, DD, b_Y2, x, (float*)Sh, DD, DD / BK);
    // F1 (fp16 out)
    gemm_kernel<0><<<gf1, 256, GEMM_SMEM>>>(Sh, DD, Wh + OW_F1, KDD, b_F1, nullptr, (float*)F1h, KDD, DD / BK);
    // F2 (fp32 out, feeds LN)
    gemm_kernel<4><<<gproj, 256, GEMM_SMEM>>>(F1h, KDD, Wh + OW_F2, DD, b_F2, nullptr, F2g, DD, KDD / BK);
    // LayerNorm -> Z
    ln_kernel<<<MROWS / 8, 256>>>(F2g, ln_g, ln_b, Z);
}